// round 10
// baseline (speedup 1.0000x reference)
#include <cuda_runtime.h>

#define SIZE 256
#define KP 64
#define NB 4
#define NPIX (SIZE * SIZE)
#define EBLK 256          // edge/norm kernel blocks (2/SM -> 296 slots >= 256: one wave)
#define NTHR 256

// ---- scratch (device globals; no allocations allowed) ----
__device__ float g_mask[NB * NPIX];
__device__ float g_bmn[EBLK];
__device__ float g_bmx[EBLK];
__device__ unsigned g_cnt = 0;
__device__ volatile unsigned g_gen = 0;

__device__ __forceinline__ float frcp(float x) { float y; asm("rcp.approx.f32 %0,%1;" : "=f"(y) : "f"(x)); return y; }
__device__ __forceinline__ float tha(float x)  { float y; asm("tanh.approx.f32 %0,%1;" : "=f"(y) : "f"(x)); return y; }

// ---- per-px-edge summand: tanh(1e5*cross) * clip(atan2(|cross|,dot)) -------
// Lagrange identity: |d||n| = sqrt(cross^2+dot^2) -> atan2 needs no norms.
__device__ __forceinline__ float summand(float cr, float dt) {
    float ac = fabsf(cr), ad = fabsf(dt);
    float mx = fmaxf(ac, ad), mn = fminf(ac, ad);
    float q = mn * frcp(mx);
    float z = q * q;
    float a = q * fmaf(z, fmaf(z, fmaf(z, fmaf(z, fmaf(z, -0.01172120f, 0.05265332f),
                   -0.11643287f), 0.19354346f), -0.33262347f), 0.99997726f);
    a = (ac > ad) ? 1.5707963267948966f - a : a;     // octant fold
    a = (dt < 0.0f) ? 3.1415926535897931f - a : a;   // dot<0 -> obtuse
    // reproduce reference clip(r, -1+1e-5, 1-1e-5) before acos:
    a = fminf(fmaxf(a, 4.4721584e-3f), 3.1371205f);
    return tha(100000.0f * cr) * a;
}

// ---------------------------------------------------------------------------
// 1. winding-number soft mask — scalar, 2 px/thread (2 independent chains,
//    shared dx), free occupancy (no grid barrier here)
// ---------------------------------------------------------------------------
__global__ void __launch_bounds__(NTHR, 4)
k_mask(const float* __restrict__ contour) {
    __shared__ float cx[KP + 1];
    __shared__ float cy[KP + 1];
    const int blk = blockIdx.x;
    const int t = threadIdx.x;
    const int b = blk >> 7;          // 128 blocks per batch
    if (t <= KP) {                   // duplicated vertex 0 -> branchless roll
        int k = t & (KP - 1);
        cx[t] = contour[b * KP * 2 + k * 2 + 0];
        cy[t] = contour[b * KP * 2 + k * 2 + 1];
    }
    __syncthreads();

    const int p0 = (blk & 127) * 512 + t * 2;    // 2 consecutive same-row px
    const float px  = (float)(p0 >> 8) * (1.0f / SIZE);
    const float py0 = (float)(p0 & 255) * (1.0f / SIZE);

    float dxp  = cx[0] - px;
    float dyp0 = cy[0] - py0;
    float dyp1 = dyp0 - (1.0f / SIZE);
    float acc0 = 0.0f, acc1 = 0.0f;

#pragma unroll 4
    for (int k = 0; k < KP; k++) {
        const float dxn  = cx[k + 1] - px;
        const float dyn0 = cy[k + 1] - py0;
        const float dyn1 = dyn0 - (1.0f / SIZE);
        const float dxx  = dxp * dxn;

        float cr0 = fmaf(dyp0, dxn, -dxp * dyn0);
        float dt0 = fmaf(dyp0, dyn0, dxx);
        acc0 += summand(cr0, dt0);

        float cr1 = fmaf(dyp1, dxn, -dxp * dyn1);
        float dt1 = fmaf(dyp1, dyn1, dxx);
        acc1 += summand(cr1, dt1);

        dxp = dxn; dyp0 = dyn0; dyp1 = dyn1;
    }

    float2 v;
    v.x = fminf(fabsf(acc0) * 0.15915494309189535f, 1.0f);
    v.y = fminf(fabsf(acc1) * 0.15915494309189535f, 1.0f);
    *(float2*)&g_mask[b * NPIX + p0] = v;
}

// ---- one-wave software grid barrier (EBLK blocks co-resident) --------------
__device__ __forceinline__ void grid_sync(unsigned& gen) {
    __syncthreads();
    if (threadIdx.x == 0) {
        gen++;
        __threadfence();
        unsigned a = atomicAdd(&g_cnt, 1);
        if (a == EBLK - 1) {
            g_cnt = 0;
            __threadfence();
            g_gen = gen;
        } else {
            while (g_gen != gen) { }
            __threadfence();
        }
    }
    __syncthreads();
}

// ---------------------------------------------------------------------------
// 2. persistent: sobel + 3x3 maxpool + block minmax (32x32 tile/block, pooled
//    values in regs) -> barrier -> batch minmax reduce + normalize
// ---------------------------------------------------------------------------
__global__ void __launch_bounds__(NTHR, 2)
k_edgenorm(float* __restrict__ out) {
    __shared__ float sm[36][37];     // mask tile 32x32 + halo 2 (pad col)
    __shared__ float sb[34][35];     // sobel tile + halo 1 (pad col)
    __shared__ float red[16];        // [0..7]=min partials, [8..15]=max partials

    const int blk = blockIdx.x;
    const int t = threadIdx.x;
    const int b = blk >> 6;          // 64 tiles per batch
    const int sub = blk & 63;
    unsigned gen = g_gen;

    const int ti = (sub >> 3) * 32;
    const int tj = (sub & 7) * 32;
    const float* __restrict__ m = g_mask + b * NPIX;

    for (int idx = t; idx < 36 * 36; idx += NTHR) {
        int si = idx / 36, sj = idx - si * 36;
        int gi = min(max(ti - 2 + si, 0), SIZE - 1);
        int gj = min(max(tj - 2 + sj, 0), SIZE - 1);
        sm[si][sj] = m[gi * SIZE + gj];
    }
    __syncthreads();

    for (int idx = t; idx < 34 * 34; idx += NTHR) {
        int si = idx / 34, sj = idx - si * 34;
        int gi = ti - 1 + si, gj = tj - 1 + sj;
        float v = 0.0f;
        if (gi > 0 && gi < SIZE - 1 && gj > 0 && gj < SIZE - 1) {
            float a00 = sm[si][sj],     a01 = sm[si][sj + 1],     a02 = sm[si][sj + 2];
            float a10 = sm[si + 1][sj],                           a12 = sm[si + 1][sj + 2];
            float a20 = sm[si + 2][sj], a21 = sm[si + 2][sj + 1], a22 = sm[si + 2][sj + 2];
            float gx = 2.0f * (a00 - a02) + 4.0f * (a10 - a12) + 2.0f * (a20 - a22);
            float gy = 2.0f * (a00 - a20) + 4.0f * (a01 - a21) + 2.0f * (a02 - a22);
            v = sqrtf(fmaxf(gx * gx + gy * gy, 1e-24f));
        }
        sb[si][sj] = v;
    }
    __syncthreads();

    const int li = t >> 3;            // 0..31 output row within tile
    const int lj = (t & 7) * 4;       // 0,4,...,28 output col base
    float w[6];
#pragma unroll
    for (int c = 0; c < 6; c++)
        w[c] = fmaxf(fmaxf(sb[li][lj + c], sb[li + 1][lj + c]), sb[li + 2][lj + c]);
    const float r0 = fmaxf(fmaxf(w[0], w[1]), w[2]);
    const float r1 = fmaxf(fmaxf(w[1], w[2]), w[3]);
    const float r2 = fmaxf(fmaxf(w[2], w[3]), w[4]);
    const float r3 = fmaxf(fmaxf(w[3], w[4]), w[5]);

    // block min/max of the 1024 pooled values
    float lmn = fminf(fminf(r0, r1), fminf(r2, r3));
    float lmx = fmaxf(fmaxf(r0, r1), fmaxf(r2, r3));
#pragma unroll
    for (int off = 16; off > 0; off >>= 1) {
        lmn = fminf(lmn, __shfl_xor_sync(0xffffffffu, lmn, off));
        lmx = fmaxf(lmx, __shfl_xor_sync(0xffffffffu, lmx, off));
    }
    {
        int lane = t & 31, wid = t >> 5;
        if (lane == 0) { red[wid] = lmn; red[8 + wid] = lmx; }
        __syncthreads();
        if (t == 0) {
            float gmn = red[0], gmx = red[8];
#pragma unroll
            for (int wq = 1; wq < 8; wq++) {
                gmn = fminf(gmn, red[wq]);
                gmx = fmaxf(gmx, red[8 + wq]);
            }
            g_bmn[blk] = gmn;
            g_bmx[blk] = gmx;
        }
    }

    grid_sync(gen);   // all block minmax published

    if (t < 64) {
        float x = g_bmn[(b << 6) + t];
        float y = g_bmx[(b << 6) + t];
#pragma unroll
        for (int off = 16; off > 0; off >>= 1) {
            x = fminf(x, __shfl_xor_sync(0xffffffffu, x, off));
            y = fmaxf(y, __shfl_xor_sync(0xffffffffu, y, off));
        }
        if ((t & 31) == 0) { red[t >> 5] = x; red[4 + (t >> 5)] = y; }
    }
    __syncthreads();
    const float mn = fminf(red[0], red[1]);
    const float mx = fmaxf(red[4], red[5]);
    const float sc = 1.0f / (mx - mn + 1e-9f);

    float4 o;
    o.x = (r0 - mn) * sc;
    o.y = (r1 - mn) * sc;
    o.z = (r2 - mn) * sc;
    o.w = (r3 - mn) * sc;
    *(float4*)&out[b * NPIX + (ti + li) * SIZE + tj + lj] = o;
}

// ---------------------------------------------------------------------------
extern "C" void kernel_launch(void* const* d_in, const int* in_sizes, int n_in,
                              void* d_out, int out_size) {
    const float* contour = (const float*)d_in[0];
    float* out = (float*)d_out;
    k_mask<<<512, NTHR>>>(contour);
    k_edgenorm<<<EBLK, NTHR>>>(out);
}

// round 11
// speedup vs baseline: 1.0470x; 1.0470x over previous
#include <cuda_runtime.h>

#define SIZE 256
#define KP 64
#define NB 4
#define NPIX (SIZE * SIZE)
#define NTHR 256

typedef unsigned long long u64;

// ---- scratch (device globals; no allocations allowed) ----
__device__ float g_mask[NB * NPIX];
__device__ float g_pool[NB * NPIX];
__device__ unsigned g_mn[NB];
__device__ unsigned g_mx[NB];

// ---- packed f32x2 helpers (Blackwell sm_100+) ----
__device__ __forceinline__ u64 pk(float lo, float hi) {
    u64 r; asm("mov.b64 %0,{%1,%2};" : "=l"(r) : "f"(lo), "f"(hi)); return r;
}
__device__ __forceinline__ u64 pk2(float s) { return pk(s, s); }
__device__ __forceinline__ void unpk(u64 v, float& lo, float& hi) {
    asm("mov.b64 {%0,%1},%2;" : "=f"(lo), "=f"(hi) : "l"(v));
}
__device__ __forceinline__ u64 pfma(u64 a, u64 b, u64 c) {
    u64 d; asm("fma.rn.f32x2 %0,%1,%2,%3;" : "=l"(d) : "l"(a), "l"(b), "l"(c)); return d;
}
__device__ __forceinline__ u64 pmul(u64 a, u64 b) {
    u64 d; asm("mul.rn.f32x2 %0,%1,%2;" : "=l"(d) : "l"(a), "l"(b)); return d;
}
__device__ __forceinline__ u64 padd(u64 a, u64 b) {
    u64 d; asm("add.rn.f32x2 %0,%1,%2;" : "=l"(d) : "l"(a), "l"(b)); return d;
}
__device__ __forceinline__ float frcp(float x) { float y; asm("rcp.approx.f32 %0,%1;" : "=f"(y) : "f"(x)); return y; }
__device__ __forceinline__ float tha(float x)  { float y; asm("tanh.approx.f32 %0,%1;" : "=f"(y) : "f"(x)); return y; }

// ---------------------------------------------------------------------------
// 0. reset per-batch min/max accumulators
// ---------------------------------------------------------------------------
__global__ void k_init() {
    int t = threadIdx.x;
    if (t < NB) {
        g_mn[t] = 0x7f7fffffu;  // FLT_MAX bits
        g_mx[t] = 0u;           // 0.0f bits (pooled values are >= 0)
    }
}

// ---- per-2-px summand: tanh(1e5*cross) * clip(atan2(|cross|,dot)) ----------
// Lagrange identity: |d||n| = sqrt(cross^2 + dot^2) -> no norms needed.
__device__ __forceinline__ u64 angle_acc(u64 CR, u64 DT, u64 ACC,
                                         u64 C0, u64 C1, u64 C2, u64 C3, u64 C4, u64 C5,
                                         u64 KB) {
    float c0, c1, d0, d1;
    unpk(CR, c0, c1); unpk(DT, d0, d1);
    float mx0 = fmaxf(fabsf(c0), fabsf(d0));
    float mx1 = fmaxf(fabsf(c1), fabsf(d1));
    float mn0 = fminf(fabsf(c0), fabsf(d0));
    float mn1 = fminf(fabsf(c1), fabsf(d1));
    float q0 = mn0 * frcp(mx0);
    float q1 = mn1 * frcp(mx1);

    u64 Q = pk(q0, q1);
    u64 Z = pmul(Q, Q);
    u64 T = C5;
    T = pfma(Z, T, C4);
    T = pfma(Z, T, C3);
    T = pfma(Z, T, C2);
    T = pfma(Z, T, C1);
    T = pfma(Z, T, C0);
    u64 A = pmul(Q, T);                       // atan(min/max) in [0, pi/4]

    float a0, a1; unpk(A, a0, a1);
    a0 = (fabsf(c0) > fabsf(d0)) ? 1.5707963267948966f - a0 : a0;   // octant fold
    a1 = (fabsf(c1) > fabsf(d1)) ? 1.5707963267948966f - a1 : a1;
    a0 = (d0 < 0.0f) ? 3.1415926535897931f - a0 : a0;   // dot<0 -> obtuse
    a1 = (d1 < 0.0f) ? 3.1415926535897931f - a1 : a1;
    // reproduce reference clip(r, -1+1e-5, 1-1e-5) before acos:
    a0 = fminf(fmaxf(a0, 4.4721584e-3f), 3.1371205f);
    a1 = fminf(fmaxf(a1, 4.4721584e-3f), 3.1371205f);

    u64 CS = pmul(KB, CR);
    float s0, s1; unpk(CS, s0, s1);
    float t0 = tha(s0), t1 = tha(s1);
    return pfma(pk(t0, t1), pk(a0, a1), ACC);
}

// ---------------------------------------------------------------------------
// 1. winding-number soft mask — hybrid packed, 2 px/thread, free occupancy
// ---------------------------------------------------------------------------
__global__ void k_mask(const float* __restrict__ contour) {
    __shared__ u64 cx2[KP + 1];      // {cx,cx} duplicated pairs -> LDS.64
    __shared__ u64 cy2[KP + 1];
    const int blk = blockIdx.x;
    const int t = threadIdx.x;
    const int b = blk >> 7;          // 128 blocks per batch
    if (t <= KP) {                   // duplicated vertex 0 -> branchless roll
        int k = t & (KP - 1);
        cx2[t] = pk2(contour[b * KP * 2 + k * 2 + 0]);
        cy2[t] = pk2(contour[b * KP * 2 + k * 2 + 1]);
    }
    __syncthreads();

    const int p0 = (blk & 127) * 512 + t * 2;    // 2 consecutive same-row px
    const float px = (float)(p0 >> 8) * (1.0f / SIZE);
    const float fy = (float)(p0 & 255) * (1.0f / SIZE);

    const u64 NPX = pk2(-px);
    const u64 NPY = pk(-fy, -(fy + 1.0f / SIZE));
    const u64 NEG1 = pk2(-1.0f);
    const u64 KB = pk2(100000.0f);
    const u64 C0 = pk2( 0.99997726f);
    const u64 C1 = pk2(-0.33262347f);
    const u64 C2 = pk2( 0.19354346f);
    const u64 C3 = pk2(-0.11643287f);
    const u64 C4 = pk2( 0.05265332f);
    const u64 C5 = pk2(-0.01172120f);

    u64 DXP = padd(cx2[0], NPX);     // {dx,dx}
    u64 DYP = padd(cy2[0], NPY);
    u64 NDXP = pmul(DXP, NEG1);
    u64 ACC = 0ull;

#pragma unroll 8
    for (int k = 0; k < KP; k++) {
        const u64 DXN = padd(cx2[k + 1], NPX);
        const u64 DYN = padd(cy2[k + 1], NPY);
        u64 CR = pfma(DYP, DXN, pmul(NDXP, DYN));
        u64 DT = pfma(DYP, DYN, pmul(DXP, DXN));
        ACC = angle_acc(CR, DT, ACC, C0, C1, C2, C3, C4, C5, KB);
        DXP = DXN; DYP = DYN; NDXP = pmul(DXN, NEG1);
    }

    float a0, a1; unpk(ACC, a0, a1);
    float2 v;
    v.x = fminf(fabsf(a0) * 0.15915494309189535f, 1.0f);
    v.y = fminf(fabsf(a1) * 0.15915494309189535f, 1.0f);
    *(float2*)&g_mask[b * NPIX + p0] = v;
}

// ---------------------------------------------------------------------------
// 2. sobel + 3x3 maxpool + per-batch atomic minmax (16x16 output tiles,
//    1024 blocks -> high occupancy, no barrier)
// ---------------------------------------------------------------------------
__global__ void k_edge() {
    __shared__ float sm[20][21];     // mask tile + halo 2 (pad col)
    __shared__ float sb[18][19];     // sobel tile + halo 1 (pad col)
    __shared__ float red[16];

    const int blk = blockIdx.x;
    const int t = threadIdx.x;
    const int b = blk >> 8;          // 256 tiles per batch
    const int tile = blk & 255;
    const int ti = (tile >> 4) * 16;
    const int tj = (tile & 15) * 16;
    const float* __restrict__ m = g_mask + b * NPIX;

    for (int idx = t; idx < 20 * 20; idx += NTHR) {
        int si = idx / 20, sj = idx - si * 20;
        int gi = min(max(ti - 2 + si, 0), SIZE - 1);
        int gj = min(max(tj - 2 + sj, 0), SIZE - 1);
        sm[si][sj] = m[gi * SIZE + gj];
    }
    __syncthreads();

    for (int idx = t; idx < 18 * 18; idx += NTHR) {
        int si = idx / 18, sj = idx - si * 18;
        int gi = ti - 1 + si, gj = tj - 1 + sj;
        float v = 0.0f;
        if (gi > 0 && gi < SIZE - 1 && gj > 0 && gj < SIZE - 1) {
            float a00 = sm[si][sj],     a01 = sm[si][sj + 1],     a02 = sm[si][sj + 2];
            float a10 = sm[si + 1][sj],                           a12 = sm[si + 1][sj + 2];
            float a20 = sm[si + 2][sj], a21 = sm[si + 2][sj + 1], a22 = sm[si + 2][sj + 2];
            float gx = 2.0f * (a00 - a02) + 4.0f * (a10 - a12) + 2.0f * (a20 - a22);
            float gy = 2.0f * (a00 - a20) + 4.0f * (a01 - a21) + 2.0f * (a02 - a22);
            v = sqrtf(fmaxf(gx * gx + gy * gy, 1e-24f));
        }
        sb[si][sj] = v;
    }
    __syncthreads();

    const int li = t >> 4;            // 0..15
    const int lj = t & 15;            // 0..15
    float mx = sb[li][lj];
    mx = fmaxf(mx, sb[li][lj + 1]);     mx = fmaxf(mx, sb[li][lj + 2]);
    mx = fmaxf(mx, sb[li + 1][lj]);     mx = fmaxf(mx, sb[li + 1][lj + 1]); mx = fmaxf(mx, sb[li + 1][lj + 2]);
    mx = fmaxf(mx, sb[li + 2][lj]);     mx = fmaxf(mx, sb[li + 2][lj + 1]); mx = fmaxf(mx, sb[li + 2][lj + 2]);
    g_pool[b * NPIX + (ti + li) * SIZE + (tj + lj)] = mx;

    // block min/max then one atomic pair
    float lmn = mx, lmx = mx;
#pragma unroll
    for (int off = 16; off > 0; off >>= 1) {
        lmn = fminf(lmn, __shfl_xor_sync(0xffffffffu, lmn, off));
        lmx = fmaxf(lmx, __shfl_xor_sync(0xffffffffu, lmx, off));
    }
    int lane = t & 31, wid = t >> 5;
    if (lane == 0) { red[wid] = lmn; red[8 + wid] = lmx; }
    __syncthreads();
    if (wid == 0) {
        lmn = (lane < 8) ? red[lane] : 3.4e38f;
        lmx = (lane < 8) ? red[8 + lane] : 0.0f;
#pragma unroll
        for (int off = 4; off > 0; off >>= 1) {
            lmn = fminf(lmn, __shfl_xor_sync(0xffffffffu, lmn, off));
            lmx = fmaxf(lmx, __shfl_xor_sync(0xffffffffu, lmx, off));
        }
        if (lane == 0) {
            atomicMin(&g_mn[b], __float_as_uint(lmn));
            atomicMax(&g_mx[b], __float_as_uint(lmx));
        }
    }
}

// ---------------------------------------------------------------------------
// 3. per-batch normalize — one thread per pixel (max parallelism)
// ---------------------------------------------------------------------------
__global__ void k_norm(float* __restrict__ out) {
    const int idx = blockIdx.x * 512 + threadIdx.x;
    const int b = idx >> 16;
    const float mn = __uint_as_float(g_mn[b]);
    const float sc = 1.0f / (__uint_as_float(g_mx[b]) - mn + 1e-9f);
    out[idx] = (g_pool[idx] - mn) * sc;
}

// ---------------------------------------------------------------------------
extern "C" void kernel_launch(void* const* d_in, const int* in_sizes, int n_in,
                              void* d_out, int out_size) {
    const float* contour = (const float*)d_in[0];
    float* out = (float*)d_out;

    k_init<<<1, 32>>>();
    k_mask<<<512, NTHR>>>(contour);
    k_edge<<<1024, NTHR>>>();
    k_norm<<<NB * NPIX / 512, 512>>>(out);
}

// round 13
// speedup vs baseline: 1.0678x; 1.0198x over previous
#include <cuda_runtime.h>

#define SIZE 256
#define KP 64
#define NB 4
#define NPIX (SIZE * SIZE)
#define NTHR 256

// ---- scratch (device globals; no allocations allowed) ----
__device__ float g_mask[NB * NPIX];
__device__ float g_pool[NB * NPIX];
__device__ unsigned g_mn[NB];
__device__ unsigned g_mx[NB];

__device__ __forceinline__ float frcp(float x) { float y; asm("rcp.approx.f32 %0,%1;" : "=f"(y) : "f"(x)); return y; }
__device__ __forceinline__ float tha(float x)  { float y; asm("tanh.approx.f32 %0,%1;" : "=f"(y) : "f"(x)); return y; }

// ---- per-px-edge summand: tanh(1e5*cross) * clip(atan2(|cross|,dot)) -------
// Lagrange identity: |d||n| = sqrt(cross^2+dot^2) -> atan2 needs no norms.
__device__ __forceinline__ float summand(float cr, float dt) {
    float ac = fabsf(cr), ad = fabsf(dt);
    float mx = fmaxf(ac, ad), mn = fminf(ac, ad);
    float q = mn * frcp(mx);
    float z = q * q;
    float a = q * fmaf(z, fmaf(z, fmaf(z, fmaf(z, fmaf(z, -0.01172120f, 0.05265332f),
                   -0.11643287f), 0.19354346f), -0.33262347f), 0.99997726f);
    a = (ac > ad) ? 1.5707963267948966f - a : a;     // octant fold
    a = (dt < 0.0f) ? 3.1415926535897931f - a : a;   // dot<0 -> obtuse
    // reproduce reference clip(r, -1+1e-5, 1-1e-5) before acos:
    a = fminf(fmaxf(a, 4.4721584e-3f), 3.1371205f);
    return tha(100000.0f * cr) * a;
}

// ---------------------------------------------------------------------------
// 1. winding-number soft mask — scalar, 1 px/thread, one block per image row
//    (px and the dx chain are block-uniform -> uniform datapath), max occupancy
//    (262144 threads = 55 warps/SM). Also performs the minmax-accumulator init.
// ---------------------------------------------------------------------------
__global__ void __launch_bounds__(NTHR, 6)
k_mask(const float* __restrict__ contour) {
    __shared__ float cx[KP + 1];
    __shared__ float cy[KP + 1];
    const int blk = blockIdx.x;      // = b*256 + row
    const int t = threadIdx.x;       // column j
    const int b = blk >> 8;
    const int row = blk & 255;

    if (blk == 0 && t < NB) {        // init for k_edge's atomics (next kernel)
        g_mn[t] = 0x7f7fffffu;       // FLT_MAX bits
        g_mx[t] = 0u;                // 0.0f bits (pooled values >= 0)
    }
    if (t <= KP) {                   // duplicated vertex 0 -> branchless roll
        int k = t & (KP - 1);
        cx[t] = contour[b * KP * 2 + k * 2 + 0];
        cy[t] = contour[b * KP * 2 + k * 2 + 1];
    }
    __syncthreads();

    const float px = (float)row * (1.0f / SIZE);   // block-uniform
    const float py = (float)t * (1.0f / SIZE);     // per-lane

    float dxp = cx[0] - px;          // block-uniform chain
    float dyp = cy[0] - py;
    float acc = 0.0f;

#pragma unroll 4
    for (int k = 0; k < KP; k++) {
        const float dxn = cx[k + 1] - px;          // uniform
        const float dyn = cy[k + 1] - py;          // per-lane
        const float cr = fmaf(dyp, dxn, -dxp * dyn);
        const float dt = fmaf(dyp, dyn, dxp * dxn); // dxp*dxn uniform
        acc += summand(cr, dt);
        dxp = dxn; dyp = dyn;
    }

    g_mask[b * NPIX + row * SIZE + t] =
        fminf(fabsf(acc) * 0.15915494309189535f, 1.0f);
}

// ---------------------------------------------------------------------------
// 2. sobel + 3x3 maxpool + per-batch atomic minmax (16x16 output tiles,
//    1024 blocks -> high occupancy, no barrier)
// ---------------------------------------------------------------------------
__global__ void k_edge() {
    __shared__ float sm[20][21];     // mask tile + halo 2 (pad col)
    __shared__ float sb[18][19];     // sobel tile + halo 1 (pad col)
    __shared__ float red[16];

    const int blk = blockIdx.x;
    const int t = threadIdx.x;
    const int b = blk >> 8;          // 256 tiles per batch
    const int tile = blk & 255;
    const int ti = (tile >> 4) * 16;
    const int tj = (tile & 15) * 16;
    const float* __restrict__ m = g_mask + b * NPIX;

    for (int idx = t; idx < 20 * 20; idx += NTHR) {
        int si = idx / 20, sj = idx - si * 20;
        int gi = min(max(ti - 2 + si, 0), SIZE - 1);
        int gj = min(max(tj - 2 + sj, 0), SIZE - 1);
        sm[si][sj] = m[gi * SIZE + gj];
    }
    __syncthreads();

    for (int idx = t; idx < 18 * 18; idx += NTHR) {
        int si = idx / 18, sj = idx - si * 18;
        int gi = ti - 1 + si, gj = tj - 1 + sj;
        float v = 0.0f;
        if (gi > 0 && gi < SIZE - 1 && gj > 0 && gj < SIZE - 1) {
            float a00 = sm[si][sj],     a01 = sm[si][sj + 1],     a02 = sm[si][sj + 2];
            float a10 = sm[si + 1][sj],                           a12 = sm[si + 1][sj + 2];
            float a20 = sm[si + 2][sj], a21 = sm[si + 2][sj + 1], a22 = sm[si + 2][sj + 2];
            float gx = 2.0f * (a00 - a02) + 4.0f * (a10 - a12) + 2.0f * (a20 - a22);
            float gy = 2.0f * (a00 - a20) + 4.0f * (a01 - a21) + 2.0f * (a02 - a22);
            v = sqrtf(fmaxf(gx * gx + gy * gy, 1e-24f));
        }
        sb[si][sj] = v;
    }
    __syncthreads();

    const int li = t >> 4;            // 0..15
    const int lj = t & 15;            // 0..15
    float mx = sb[li][lj];
    mx = fmaxf(mx, sb[li][lj + 1]);     mx = fmaxf(mx, sb[li][lj + 2]);
    mx = fmaxf(mx, sb[li + 1][lj]);     mx = fmaxf(mx, sb[li + 1][lj + 1]); mx = fmaxf(mx, sb[li + 1][lj + 2]);
    mx = fmaxf(mx, sb[li + 2][lj]);     mx = fmaxf(mx, sb[li + 2][lj + 1]); mx = fmaxf(mx, sb[li + 2][lj + 2]);
    g_pool[b * NPIX + (ti + li) * SIZE + (tj + lj)] = mx;

    // block min/max then one atomic pair
    float lmn = mx, lmx = mx;
#pragma unroll
    for (int off = 16; off > 0; off >>= 1) {
        lmn = fminf(lmn, __shfl_xor_sync(0xffffffffu, lmn, off));
        lmx = fmaxf(lmx, __shfl_xor_sync(0xffffffffu, lmx, off));
    }
    int lane = t & 31, wid = t >> 5;
    if (lane == 0) { red[wid] = lmn; red[8 + wid] = lmx; }
    __syncthreads();
    if (wid == 0) {
        lmn = (lane < 8) ? red[lane] : 3.4e38f;
        lmx = (lane < 8) ? red[8 + lane] : 0.0f;
#pragma unroll
        for (int off = 4; off > 0; off >>= 1) {
            lmn = fminf(lmn, __shfl_xor_sync(0xffffffffu, lmn, off));
            lmx = fmaxf(lmx, __shfl_xor_sync(0xffffffffu, lmx, off));
        }
        if (lane == 0) {
            atomicMin(&g_mn[b], __float_as_uint(lmn));
            atomicMax(&g_mx[b], __float_as_uint(lmx));
        }
    }
}

// ---------------------------------------------------------------------------
// 3. per-batch normalize — float4 vectorized
// ---------------------------------------------------------------------------
__global__ void k_norm(float* __restrict__ out) {
    const int q = blockIdx.x * 512 + threadIdx.x;   // float4 index
    const int b = q >> 14;                          // 16384 float4 per batch
    const float mn = __uint_as_float(g_mn[b]);
    const float sc = 1.0f / (__uint_as_float(g_mx[b]) - mn + 1e-9f);
    float4 v = ((const float4*)g_pool)[q];
    v.x = (v.x - mn) * sc;
    v.y = (v.y - mn) * sc;
    v.z = (v.z - mn) * sc;
    v.w = (v.w - mn) * sc;
    ((float4*)out)[q] = v;
}

// ---------------------------------------------------------------------------
extern "C" void kernel_launch(void* const* d_in, const int* in_sizes, int n_in,
                              void* d_out, int out_size) {
    const float* contour = (const float*)d_in[0];
    float* out = (float*)d_out;

    k_mask<<<NB * SIZE, NTHR>>>(contour);     // 1024 blocks: one per image row
    k_edge<<<1024, NTHR>>>();
    k_norm<<<NB * NPIX / 4 / 512, 512>>>(out);
}

// round 14
// speedup vs baseline: 1.1228x; 1.0515x over previous
#include <cuda_runtime.h>

#define SIZE 256
#define KP 64
#define NB 4
#define NPIX (SIZE * SIZE)
#define NTHR 256

// coordinate pre-scale: s = sqrt(1e5) so that cross products carry the
// reference's 1e5 tanh gain implicitly (angles/ratios are scale-invariant)
#define CSCALE 316.22776601683793f

// ---- scratch (device globals; no allocations allowed) ----
__device__ float g_mask[NB * NPIX];
__device__ float g_pool[NB * NPIX];
__device__ unsigned g_mn[NB];
__device__ unsigned g_mx[NB];

__device__ __forceinline__ float rsqa(float x) { float y; asm("rsqrt.approx.f32 %0,%1;" : "=f"(y) : "f"(x)); return y; }
__device__ __forceinline__ float sqa(float x)  { float y; asm("sqrt.approx.f32 %0,%1;"  : "=f"(y) : "f"(x)); return y; }
__device__ __forceinline__ float frcp(float x) { float y; asm("rcp.approx.f32 %0,%1;"  : "=f"(y) : "f"(x)); return y; }
__device__ __forceinline__ float tha(float x)  { float y; asm("tanh.approx.f32 %0,%1;" : "=f"(y) : "f"(x)); return y; }

// ---------------------------------------------------------------------------
// 1. winding-number soft mask — scalar, 1 px/thread, one block per image row.
//    Summand = tanh(cr) * acos(clip(dt*rsqrt(cr^2+dt^2), -1+1e-5, 1-1e-5))
//    (Lagrange: cr^2+dt^2 = |d|^2|n|^2, so this matches the reference's
//    dot/(|d||n|) exactly; coords pre-scaled so cr already carries the 1e5.)
//    acos via A&S 4.4.46 (|err| ~ 2e-8): select-free, only 2 alu-class ops.
// ---------------------------------------------------------------------------
__global__ void __launch_bounds__(NTHR, 6)
k_mask(const float* __restrict__ contour) {
    __shared__ float cx[KP + 1];
    __shared__ float cy[KP + 1];
    const int blk = blockIdx.x;      // = b*256 + row
    const int t = threadIdx.x;       // column j
    const int b = blk >> 8;
    const int row = blk & 255;

    if (blk == 0 && t < NB) {        // init for k_edge's atomics (next kernel)
        g_mn[t] = 0x7f7fffffu;       // FLT_MAX bits
        g_mx[t] = 0u;                // 0.0f bits (pooled values >= 0)
    }
    if (t <= KP) {                   // duplicated vertex 0 -> branchless roll
        int k = t & (KP - 1);
        cx[t] = CSCALE * contour[b * KP * 2 + k * 2 + 0];
        cy[t] = CSCALE * contour[b * KP * 2 + k * 2 + 1];
    }
    __syncthreads();

    const float px = (float)row * (CSCALE / SIZE);   // block-uniform
    const float py = (float)t * (CSCALE / SIZE);     // per-lane

    float dxp = cx[0] - px;
    float dyp = cy[0] - py;
    float acc = 0.0f;

#pragma unroll 8
    for (int k = 0; k < KP; k++) {
        const float dxn = cx[k + 1] - px;
        const float dyn = cy[k + 1] - py;
        const float cr = fmaf(dyp, dxn, -dxp * dyn);   // = 1e5 * cross_orig
        const float dt = fmaf(dyp, dyn, dxp * dxn);

        const float prod = fmaf(cr, cr, dt * dt);      // (|d||n|)^2 (scaled^4)
        const float r = dt * rsqa(prod);               // cos(angle)
        const float e = copysignf(1.0f, r);
        const float x = fminf(fabsf(r), 0.99999f);     // reference clip 1-1e-5
        const float s = sqa(1.0f - x);
        float p = fmaf(x, fmaf(x, fmaf(x, fmaf(x, fmaf(x, fmaf(x, fmaf(x,
                  -0.0012624911f, 0.0066700901f), -0.0170881256f),
                   0.0308918810f), -0.0501743046f), 0.0889789874f),
                  -0.2145988016f), 1.5707963050f);
        const float pos = s * p;                       // acos(x), x in [0,1)
        const float ang = fmaf(e, pos,
                          fmaf(e, -1.5707963267948966f, 1.5707963267948966f));
        acc = fmaf(tha(cr), ang, acc);

        dxp = dxn; dyp = dyn;
    }

    g_mask[b * NPIX + row * SIZE + t] =
        fminf(fabsf(acc) * 0.15915494309189535f, 1.0f);
}

// ---------------------------------------------------------------------------
// 2. sobel + 3x3 maxpool + per-batch atomic minmax (16x16 output tiles,
//    1024 blocks -> high occupancy, no barrier)
// ---------------------------------------------------------------------------
__global__ void k_edge() {
    __shared__ float sm[20][21];     // mask tile + halo 2 (pad col)
    __shared__ float sb[18][19];     // sobel tile + halo 1 (pad col)
    __shared__ float red[16];

    const int blk = blockIdx.x;
    const int t = threadIdx.x;
    const int b = blk >> 8;          // 256 tiles per batch
    const int tile = blk & 255;
    const int ti = (tile >> 4) * 16;
    const int tj = (tile & 15) * 16;
    const float* __restrict__ m = g_mask + b * NPIX;

    for (int idx = t; idx < 20 * 20; idx += NTHR) {
        int si = idx / 20, sj = idx - si * 20;
        int gi = min(max(ti - 2 + si, 0), SIZE - 1);
        int gj = min(max(tj - 2 + sj, 0), SIZE - 1);
        sm[si][sj] = m[gi * SIZE + gj];
    }
    __syncthreads();

    for (int idx = t; idx < 18 * 18; idx += NTHR) {
        int si = idx / 18, sj = idx - si * 18;
        int gi = ti - 1 + si, gj = tj - 1 + sj;
        float v = 0.0f;
        if (gi > 0 && gi < SIZE - 1 && gj > 0 && gj < SIZE - 1) {
            float a00 = sm[si][sj],     a01 = sm[si][sj + 1],     a02 = sm[si][sj + 2];
            float a10 = sm[si + 1][sj],                           a12 = sm[si + 1][sj + 2];
            float a20 = sm[si + 2][sj], a21 = sm[si + 2][sj + 1], a22 = sm[si + 2][sj + 2];
            float gx = 2.0f * (a00 - a02) + 4.0f * (a10 - a12) + 2.0f * (a20 - a22);
            float gy = 2.0f * (a00 - a20) + 4.0f * (a01 - a21) + 2.0f * (a02 - a22);
            v = sqrtf(fmaxf(gx * gx + gy * gy, 1e-24f));
        }
        sb[si][sj] = v;
    }
    __syncthreads();

    const int li = t >> 4;            // 0..15
    const int lj = t & 15;            // 0..15
    float mx = sb[li][lj];
    mx = fmaxf(mx, sb[li][lj + 1]);     mx = fmaxf(mx, sb[li][lj + 2]);
    mx = fmaxf(mx, sb[li + 1][lj]);     mx = fmaxf(mx, sb[li + 1][lj + 1]); mx = fmaxf(mx, sb[li + 1][lj + 2]);
    mx = fmaxf(mx, sb[li + 2][lj]);     mx = fmaxf(mx, sb[li + 2][lj + 1]); mx = fmaxf(mx, sb[li + 2][lj + 2]);
    g_pool[b * NPIX + (ti + li) * SIZE + (tj + lj)] = mx;

    // block min/max then one atomic pair
    float lmn = mx, lmx = mx;
#pragma unroll
    for (int off = 16; off > 0; off >>= 1) {
        lmn = fminf(lmn, __shfl_xor_sync(0xffffffffu, lmn, off));
        lmx = fmaxf(lmx, __shfl_xor_sync(0xffffffffu, lmx, off));
    }
    int lane = t & 31, wid = t >> 5;
    if (lane == 0) { red[wid] = lmn; red[8 + wid] = lmx; }
    __syncthreads();
    if (wid == 0) {
        lmn = (lane < 8) ? red[lane] : 3.4e38f;
        lmx = (lane < 8) ? red[8 + lane] : 0.0f;
#pragma unroll
        for (int off = 4; off > 0; off >>= 1) {
            lmn = fminf(lmn, __shfl_xor_sync(0xffffffffu, lmn, off));
            lmx = fmaxf(lmx, __shfl_xor_sync(0xffffffffu, lmx, off));
        }
        if (lane == 0) {
            atomicMin(&g_mn[b], __float_as_uint(lmn));
            atomicMax(&g_mx[b], __float_as_uint(lmx));
        }
    }
}

// ---------------------------------------------------------------------------
// 3. per-batch normalize — float4 vectorized, rcp.approx scale
// ---------------------------------------------------------------------------
__global__ void k_norm(float* __restrict__ out) {
    const int q = blockIdx.x * 512 + threadIdx.x;   // float4 index
    const int b = q >> 14;                          // 16384 float4 per batch
    const float mn = __uint_as_float(g_mn[b]);
    const float sc = frcp(__uint_as_float(g_mx[b]) - mn + 1e-9f);
    float4 v = ((const float4*)g_pool)[q];
    v.x = (v.x - mn) * sc;
    v.y = (v.y - mn) * sc;
    v.z = (v.z - mn) * sc;
    v.w = (v.w - mn) * sc;
    ((float4*)out)[q] = v;
}

// ---------------------------------------------------------------------------
extern "C" void kernel_launch(void* const* d_in, const int* in_sizes, int n_in,
                              void* d_out, int out_size) {
    const float* contour = (const float*)d_in[0];
    float* out = (float*)d_out;

    k_mask<<<NB * SIZE, NTHR>>>(contour);     // 1024 blocks: one per image row
    k_edge<<<1024, NTHR>>>();
    k_norm<<<NB * NPIX / 4 / 512, 512>>>(out);
}

// round 16
// speedup vs baseline: 1.2293x; 1.0948x over previous
#include <cuda_runtime.h>

#define SIZE 256
#define KP 64
#define NB 4
#define NPIX (SIZE * SIZE)
#define NTHR 256

// coordinate pre-scale: s = sqrt(1e5) so cross products carry the reference's
// 1e5 tanh gain implicitly (angles/ratios are scale-invariant)
#define CSCALE 316.22776601683793f

// ---- scratch (device globals; no allocations allowed) ----
__device__ float g_mask[NB * NPIX];
__device__ float g_pool[NB * NPIX];
__device__ unsigned g_mn[NB];
__device__ unsigned g_mx[NB];

__device__ __forceinline__ float rsqa(float x) { float y; asm("rsqrt.approx.f32 %0,%1;" : "=f"(y) : "f"(x)); return y; }
__device__ __forceinline__ float sqa(float x)  { float y; asm("sqrt.approx.f32 %0,%1;"  : "=f"(y) : "f"(x)); return y; }
__device__ __forceinline__ float frcp(float x) { float y; asm("rcp.approx.f32 %0,%1;"  : "=f"(y) : "f"(x)); return y; }
__device__ __forceinline__ float tha(float x)  { float y; asm("tanh.approx.f32 %0,%1;" : "=f"(y) : "f"(x)); return y; }

// ---------------------------------------------------------------------------
// 1. winding-number soft mask — scalar, 1 px/thread, one block per image row.
//    Block-uniform px is pre-subtracted into the shared contour table
//    ({cx-px, cy} float2 -> one LDS.64 per edge). Summand =
//    tanh(cr) * acos(clip(dt*rsqrt(cr^2+dt^2), -1+1e-5, 1-1e-5)),
//    acos via A&S 4.4.45 deg-3 (|err| ~ 5e-5).
//    launch_bounds(256,8): 32-reg target -> 2048 thr/SM -> single wave.
// ---------------------------------------------------------------------------
__global__ void __launch_bounds__(NTHR, 8)
k_mask(const float* __restrict__ contour) {
    __shared__ float2 sxy[KP + 1];   // {cx*CSCALE - px, cy*CSCALE}
    const int blk = blockIdx.x;      // = b*256 + row
    const int t = threadIdx.x;       // column j
    const int b = blk >> 8;
    const int row = blk & 255;

    if (blk == 0 && t < NB) {        // init for k_edge's atomics (next kernel)
        g_mn[t] = 0x7f7fffffu;       // FLT_MAX bits
        g_mx[t] = 0u;                // 0.0f bits (pooled values >= 0)
    }
    if (t <= KP) {                   // duplicated vertex 0 -> branchless roll
        int k = t & (KP - 1);
        float px = (float)row * (CSCALE / SIZE);
        sxy[t] = make_float2(
            fmaf(CSCALE, contour[b * KP * 2 + k * 2 + 0], -px),
            CSCALE * contour[b * KP * 2 + k * 2 + 1]);
    }
    __syncthreads();

    const float py = (float)t * (CSCALE / SIZE);   // per-lane

    float2 c0 = sxy[0];
    float dxp = c0.x;
    float dyp = c0.y - py;
    float acc = 0.0f;

#pragma unroll 8
    for (int k = 0; k < KP; k++) {
        const float2 c = sxy[k + 1];               // LDS.64
        const float dxn = c.x;                     // cx - px (pre-subtracted)
        const float dyn = c.y - py;
        const float cr = fmaf(dyp, dxn, -dxp * dyn);   // = 1e5 * cross_orig
        const float dt = fmaf(dyp, dyn, dxp * dxn);

        const float prod = fmaf(cr, cr, dt * dt);      // (|d||n|)^2
        const float r = dt * rsqa(prod);               // cos(angle)
        const float e = copysignf(1.0f, r);
        const float x = fminf(fabsf(r), 0.99999f);     // reference clip 1-1e-5
        const float s = sqa(1.0f - x);
        float p = fmaf(x, fmaf(x, fmaf(x,
                  -0.0187293f, 0.0742610f), -0.2121144f), 1.5707288f);
        const float pos = s * p;                       // acos(x), x in [0,1)
        const float ang = fmaf(e, pos,
                          fmaf(e, -1.5707963267948966f, 1.5707963267948966f));
        acc = fmaf(tha(cr), ang, acc);

        dxp = dxn; dyp = dyn;
    }

    g_mask[b * NPIX + row * SIZE + t] =
        fminf(fabsf(acc) * 0.15915494309189535f, 1.0f);
}

// ---------------------------------------------------------------------------
// 2. sobel + 3x3 maxpool + per-batch atomic minmax (16x16 output tiles,
//    1024 blocks -> high occupancy, no barrier)
// ---------------------------------------------------------------------------
__global__ void k_edge() {
    __shared__ float sm[20][21];     // mask tile + halo 2 (pad col)
    __shared__ float sb[18][19];     // sobel tile + halo 1 (pad col)
    __shared__ float red[16];

    const int blk = blockIdx.x;
    const int t = threadIdx.x;
    const int b = blk >> 8;          // 256 tiles per batch
    const int tile = blk & 255;
    const int ti = (tile >> 4) * 16;
    const int tj = (tile & 15) * 16;
    const float* __restrict__ m = g_mask + b * NPIX;

    for (int idx = t; idx < 20 * 20; idx += NTHR) {
        int si = idx / 20, sj = idx - si * 20;
        int gi = min(max(ti - 2 + si, 0), SIZE - 1);
        int gj = min(max(tj - 2 + sj, 0), SIZE - 1);
        sm[si][sj] = m[gi * SIZE + gj];
    }
    __syncthreads();

    for (int idx = t; idx < 18 * 18; idx += NTHR) {
        int si = idx / 18, sj = idx - si * 18;
        int gi = ti - 1 + si, gj = tj - 1 + sj;
        float v = 0.0f;
        if (gi > 0 && gi < SIZE - 1 && gj > 0 && gj < SIZE - 1) {
            float a00 = sm[si][sj],     a01 = sm[si][sj + 1],     a02 = sm[si][sj + 2];
            float a10 = sm[si + 1][sj],                           a12 = sm[si + 1][sj + 2];
            float a20 = sm[si + 2][sj], a21 = sm[si + 2][sj + 1], a22 = sm[si + 2][sj + 2];
            float gx = 2.0f * (a00 - a02) + 4.0f * (a10 - a12) + 2.0f * (a20 - a22);
            float gy = 2.0f * (a00 - a20) + 4.0f * (a01 - a21) + 2.0f * (a02 - a22);
            v = sqrtf(fmaxf(gx * gx + gy * gy, 1e-24f));
        }
        sb[si][sj] = v;
    }
    __syncthreads();

    const int li = t >> 4;            // 0..15
    const int lj = t & 15;            // 0..15
    float mx = sb[li][lj];
    mx = fmaxf(mx, sb[li][lj + 1]);     mx = fmaxf(mx, sb[li][lj + 2]);
    mx = fmaxf(mx, sb[li + 1][lj]);     mx = fmaxf(mx, sb[li + 1][lj + 1]); mx = fmaxf(mx, sb[li + 1][lj + 2]);
    mx = fmaxf(mx, sb[li + 2][lj]);     mx = fmaxf(mx, sb[li + 2][lj + 1]); mx = fmaxf(mx, sb[li + 2][lj + 2]);
    g_pool[b * NPIX + (ti + li) * SIZE + (tj + lj)] = mx;

    // block min/max then one atomic pair
    float lmn = mx, lmx = mx;
#pragma unroll
    for (int off = 16; off > 0; off >>= 1) {
        lmn = fminf(lmn, __shfl_xor_sync(0xffffffffu, lmn, off));
        lmx = fmaxf(lmx, __shfl_xor_sync(0xffffffffu, lmx, off));
    }
    int lane = t & 31, wid = t >> 5;
    if (lane == 0) { red[wid] = lmn; red[8 + wid] = lmx; }
    __syncthreads();
    if (wid == 0) {
        lmn = (lane < 8) ? red[lane] : 3.4e38f;
        lmx = (lane < 8) ? red[8 + lane] : 0.0f;
#pragma unroll
        for (int off = 4; off > 0; off >>= 1) {
            lmn = fminf(lmn, __shfl_xor_sync(0xffffffffu, lmn, off));
            lmx = fmaxf(lmx, __shfl_xor_sync(0xffffffffu, lmx, off));
        }
        if (lane == 0) {
            atomicMin(&g_mn[b], __float_as_uint(lmn));
            atomicMax(&g_mx[b], __float_as_uint(lmx));
        }
    }
}

// ---------------------------------------------------------------------------
// 3. per-batch normalize — float4 vectorized, rcp.approx scale
// ---------------------------------------------------------------------------
__global__ void k_norm(float* __restrict__ out) {
    const int q = blockIdx.x * 512 + threadIdx.x;   // float4 index
    const int b = q >> 14;                          // 16384 float4 per batch
    const float mn = __uint_as_float(g_mn[b]);
    const float sc = frcp(__uint_as_float(g_mx[b]) - mn + 1e-9f);
    float4 v = ((const float4*)g_pool)[q];
    v.x = (v.x - mn) * sc;
    v.y = (v.y - mn) * sc;
    v.z = (v.z - mn) * sc;
    v.w = (v.w - mn) * sc;
    ((float4*)out)[q] = v;
}

// ---------------------------------------------------------------------------
extern "C" void kernel_launch(void* const* d_in, const int* in_sizes, int n_in,
                              void* d_out, int out_size) {
    const float* contour = (const float*)d_in[0];
    float* out = (float*)d_out;

    k_mask<<<NB * SIZE, NTHR>>>(contour);     // 1024 blocks: one per image row
    k_edge<<<1024, NTHR>>>();
    k_norm<<<NB * NPIX / 4 / 512, 512>>>(out);
}

// round 17
// speedup vs baseline: 1.2929x; 1.0518x over previous
#include <cuda_runtime.h>

#define SIZE 256
#define KP 64
#define NB 4
#define NPIX (SIZE * SIZE)
#define NTHR 256

// coordinate pre-scale: CSCALE^2 = 1e5 so cross products carry the reference's
// 1e5 tanh gain implicitly (angles/ratios are scale-invariant)
#define CSCALE 316.22776601683793f

// ---- scratch (device globals; no allocations allowed) ----
__device__ float g_mask[NB * NPIX];
__device__ float g_pool[NB * NPIX];
__device__ unsigned g_mn[NB];
__device__ unsigned g_mx[NB];

__device__ __forceinline__ float rsqa(float x) { float y; asm("rsqrt.approx.f32 %0,%1;" : "=f"(y) : "f"(x)); return y; }
__device__ __forceinline__ float sqa(float x)  { float y; asm("sqrt.approx.f32 %0,%1;"  : "=f"(y) : "f"(x)); return y; }
__device__ __forceinline__ float frcp(float x) { float y; asm("rcp.approx.f32 %0,%1;"  : "=f"(y) : "f"(x)); return y; }
__device__ __forceinline__ float tha(float x)  { float y; asm("tanh.approx.f32 %0,%1;" : "=f"(y) : "f"(x)); return y; }

// ---------------------------------------------------------------------------
// 1. winding-number soft mask — 1 px/thread, one block per image row.
//    Per-edge block-uniform constants {A,B,S,C} absorb px and the vertex pair:
//      cr = A + py*B           (= 1e5 * cross_orig via CSCALE^2)
//      dt = fmaf(py, py-S, C)  (= dot, same scale)
//    -> inner loop has NO loop-carried state: LDS.128 + 3 FMA-ops + tail.
//    acos via A&S 4.4.45 deg-3; tanh/rsqrt/sqrt on MUFU.
// ---------------------------------------------------------------------------
__global__ void __launch_bounds__(NTHR, 8)
k_mask(const float* __restrict__ contour) {
    __shared__ float4 sE[KP];        // {A, B, S, C} per edge
    const int blk = blockIdx.x;      // = b*256 + row
    const int t = threadIdx.x;       // column j
    const int b = blk >> 8;
    const int row = blk & 255;

    if (blk == 0 && t < NB) {        // init for k_edge's atomics (next kernel)
        g_mn[t] = 0x7f7fffffu;       // FLT_MAX bits
        g_mx[t] = 0u;                // 0.0f bits (pooled values >= 0)
    }
    if (t < KP) {                    // edge t: vertices t and (t+1)&63
        const float px = (float)row * (CSCALE / SIZE);
        const int k1 = (t + 1) & (KP - 1);
        const float xk  = fmaf(CSCALE, contour[b * KP * 2 + t  * 2 + 0], -px);
        const float yk  = CSCALE * contour[b * KP * 2 + t  * 2 + 1];
        const float xk1 = fmaf(CSCALE, contour[b * KP * 2 + k1 * 2 + 0], -px);
        const float yk1 = CSCALE * contour[b * KP * 2 + k1 * 2 + 1];
        sE[t] = make_float4(
            fmaf(yk, xk1, -xk * yk1),   // A = yk*dxn - dxp*yk1
            xk - xk1,                   // B = dxp - dxn
            yk + yk1,                   // S
            fmaf(yk, yk1, xk * xk1));   // C = yk*yk1 + dxp*dxn
    }
    __syncthreads();

    const float py = (float)t * (CSCALE / SIZE);   // per-lane
    float acc = 0.0f;

#pragma unroll 8
    for (int k = 0; k < KP; k++) {
        const float4 E = sE[k];                    // LDS.128 (broadcast)
        const float cr = fmaf(py, E.y, E.x);       // cross (scaled by 1e5)
        const float dt = fmaf(py, py - E.z, E.w);  // dot

        const float prod = fmaf(cr, cr, dt * dt);  // (|d||n|)^2
        const float r = dt * rsqa(prod);           // cos(angle)
        const float e = copysignf(1.0f, r);
        const float x = fminf(fabsf(r), 0.99999f); // reference clip 1-1e-5
        const float s = sqa(1.0f - x);
        float p = fmaf(x, fmaf(x, fmaf(x,
                  -0.0187293f, 0.0742610f), -0.2121144f), 1.5707288f);
        const float pos = s * p;                   // acos(x), x in [0,1)
        const float ang = fmaf(e, pos - 1.5707963267948966f,
                               1.5707963267948966f);
        acc = fmaf(tha(cr), ang, acc);
    }

    g_mask[b * NPIX + row * SIZE + t] =
        fminf(fabsf(acc) * 0.15915494309189535f, 1.0f);
}

// ---------------------------------------------------------------------------
// 2. sobel + 3x3 maxpool + per-batch atomic minmax (16x16 output tiles,
//    1024 blocks -> high occupancy, no barrier)
// ---------------------------------------------------------------------------
__global__ void k_edge() {
    __shared__ float sm[20][21];     // mask tile + halo 2 (pad col)
    __shared__ float sb[18][19];     // sobel tile + halo 1 (pad col)
    __shared__ float red[16];

    const int blk = blockIdx.x;
    const int t = threadIdx.x;
    const int b = blk >> 8;          // 256 tiles per batch
    const int tile = blk & 255;
    const int ti = (tile >> 4) * 16;
    const int tj = (tile & 15) * 16;
    const float* __restrict__ m = g_mask + b * NPIX;

    for (int idx = t; idx < 20 * 20; idx += NTHR) {
        int si = idx / 20, sj = idx - si * 20;
        int gi = min(max(ti - 2 + si, 0), SIZE - 1);
        int gj = min(max(tj - 2 + sj, 0), SIZE - 1);
        sm[si][sj] = m[gi * SIZE + gj];
    }
    __syncthreads();

    for (int idx = t; idx < 18 * 18; idx += NTHR) {
        int si = idx / 18, sj = idx - si * 18;
        int gi = ti - 1 + si, gj = tj - 1 + sj;
        float v = 0.0f;
        if (gi > 0 && gi < SIZE - 1 && gj > 0 && gj < SIZE - 1) {
            float a00 = sm[si][sj],     a01 = sm[si][sj + 1],     a02 = sm[si][sj + 2];
            float a10 = sm[si + 1][sj],                           a12 = sm[si + 1][sj + 2];
            float a20 = sm[si + 2][sj], a21 = sm[si + 2][sj + 1], a22 = sm[si + 2][sj + 2];
            float gx = 2.0f * (a00 - a02) + 4.0f * (a10 - a12) + 2.0f * (a20 - a22);
            float gy = 2.0f * (a00 - a20) + 4.0f * (a01 - a21) + 2.0f * (a02 - a22);
            v = sqrtf(fmaxf(gx * gx + gy * gy, 1e-24f));
        }
        sb[si][sj] = v;
    }
    __syncthreads();

    const int li = t >> 4;            // 0..15
    const int lj = t & 15;            // 0..15
    float mx = sb[li][lj];
    mx = fmaxf(mx, sb[li][lj + 1]);     mx = fmaxf(mx, sb[li][lj + 2]);
    mx = fmaxf(mx, sb[li + 1][lj]);     mx = fmaxf(mx, sb[li + 1][lj + 1]); mx = fmaxf(mx, sb[li + 1][lj + 2]);
    mx = fmaxf(mx, sb[li + 2][lj]);     mx = fmaxf(mx, sb[li + 2][lj + 1]); mx = fmaxf(mx, sb[li + 2][lj + 2]);
    g_pool[b * NPIX + (ti + li) * SIZE + (tj + lj)] = mx;

    // block min/max then one atomic pair
    float lmn = mx, lmx = mx;
#pragma unroll
    for (int off = 16; off > 0; off >>= 1) {
        lmn = fminf(lmn, __shfl_xor_sync(0xffffffffu, lmn, off));
        lmx = fmaxf(lmx, __shfl_xor_sync(0xffffffffu, lmx, off));
    }
    int lane = t & 31, wid = t >> 5;
    if (lane == 0) { red[wid] = lmn; red[8 + wid] = lmx; }
    __syncthreads();
    if (wid == 0) {
        lmn = (lane < 8) ? red[lane] : 3.4e38f;
        lmx = (lane < 8) ? red[8 + lane] : 0.0f;
#pragma unroll
        for (int off = 4; off > 0; off >>= 1) {
            lmn = fminf(lmn, __shfl_xor_sync(0xffffffffu, lmn, off));
            lmx = fmaxf(lmx, __shfl_xor_sync(0xffffffffu, lmx, off));
        }
        if (lane == 0) {
            atomicMin(&g_mn[b], __float_as_uint(lmn));
            atomicMax(&g_mx[b], __float_as_uint(lmx));
        }
    }
}

// ---------------------------------------------------------------------------
// 3. per-batch normalize — float4 vectorized, rcp.approx scale
// ---------------------------------------------------------------------------
__global__ void k_norm(float* __restrict__ out) {
    const int q = blockIdx.x * 512 + threadIdx.x;   // float4 index
    const int b = q >> 14;                          // 16384 float4 per batch
    const float mn = __uint_as_float(g_mn[b]);
    const float sc = frcp(__uint_as_float(g_mx[b]) - mn + 1e-9f);
    float4 v = ((const float4*)g_pool)[q];
    v.x = (v.x - mn) * sc;
    v.y = (v.y - mn) * sc;
    v.z = (v.z - mn) * sc;
    v.w = (v.w - mn) * sc;
    ((float4*)out)[q] = v;
}

// ---------------------------------------------------------------------------
extern "C" void kernel_launch(void* const* d_in, const int* in_sizes, int n_in,
                              void* d_out, int out_size) {
    const float* contour = (const float*)d_in[0];
    float* out = (float*)d_out;

    k_mask<<<NB * SIZE, NTHR>>>(contour);     // 1024 blocks: one per image row
    k_edge<<<1024, NTHR>>>();
    k_norm<<<NB * NPIX / 4 / 512, 512>>>(out);
}